// round 15
// baseline (speedup 1.0000x reference)
#include <cuda_runtime.h>
#include <cuda_fp16.h>
#include <cstdint>

// ---------------------------------------------------------------------------
// DynamicDWConv on GB300 (compute_103 PTX => mma.sync fp16 + cp.async + ldmatrix)
// conv3x3(VALID)+lrelu -> conv3x3(VALID)+lrelu -> global avg pool ->
// 1x1 kernel-gen -> depthwise 3x3 SAME + bias.   B=16, C=256, H=W=64.
//
// Convs as implicit GEMM: pixels=M, couts=N, K=cin, accumulated over 9 taps.
// NHWC pixel index n=y*64+x; tap (ky,kx) input = row slice at n+ky*64+kx.
// Round 13: R11 mainloop (per-iteration A+B staging), 2-stage cp.async ring
// => 73.7KB smem/CTA => 3 CTAs/SM (24 warps), single barrier per iteration.
// ---------------------------------------------------------------------------

#define B_   16
#define C_   256
#define H_   64
#define W_   64
#define FR_  4288            // 67*64 padded NHWC frame rows per batch
#define NT1_ 32              // conv1 pixel tiles (4096/128)
#define NT2_ 30              // conv2 pixel tiles (3840/128)

// smem tile geometry: 128 rows x 64 halves (128B), row stride 144B
#define ROWB_   144
#define TILEB_  18432        // 128*144 per A (or B) tile
#define BUFB_   36864        // A|B buffer
#define NSTAGE_ 2

// Scratch (__device__ globals; allocation-free). fp16 operands.
__device__ __half g_xT [(size_t)B_ * FR_ * C_];   // kin NHWC (~35MB)
__device__ __half g_h1T[(size_t)B_ * FR_ * C_];   // lrelu(conv1) NHWC
__device__ __half g_wT [2 * 9 * 256 * 256];       // [which][tap][cout][cin]
__device__ float g_ppart[NT2_ * B_ * C_];
__device__ float g_p[B_ * C_];
__device__ float g_kern[B_ * 9 * C_];

__device__ __forceinline__ float lrelu(float v) { return v > 0.f ? v : 0.1f * v; }
__device__ __forceinline__ uint32_t smem_u32(const void* p) {
    uint32_t a;
    asm("{ .reg .u64 t; cvta.to.shared.u64 t, %1; cvt.u32.u64 %0, t; }" : "=r"(a) : "l"(p));
    return a;
}
__device__ __forceinline__ void cp16(uint32_t s, const void* g) {
    asm volatile("cp.async.cg.shared.global [%0], [%1], 16;" :: "r"(s), "l"(g) : "memory");
}
#define CP_COMMIT() asm volatile("cp.async.commit_group;" ::: "memory")
#define CP_WAIT0()  asm volatile("cp.async.wait_group 0;" ::: "memory")

#define LDSM_X4(r, addr) \
    asm volatile("ldmatrix.sync.aligned.m8n8.x4.shared.b16 {%0,%1,%2,%3}, [%4];" \
        : "=r"((r)[0]), "=r"((r)[1]), "=r"((r)[2]), "=r"((r)[3]) : "r"(addr))

#define MMA_F16(d, a, bq) \
    asm volatile("mma.sync.aligned.m16n8k16.row.col.f32.f16.f16.f32 " \
        "{%0,%1,%2,%3}, {%4,%5,%6,%7}, {%8,%9}, {%0,%1,%2,%3};" \
        : "+f"((d)[0]), "+f"((d)[1]), "+f"((d)[2]), "+f"((d)[3]) \
        : "r"((a)[0]), "r"((a)[1]), "r"((a)[2]), "r"((a)[3]), \
          "r"((bq)[0]), "r"((bq)[1]))

// ---------------------------------------------------------------------------
// Prep: w [cout][cin][3][3] fp32 -> g_wT[which][tap][cout][cin] fp16
// ---------------------------------------------------------------------------
__global__ void prep_w_kernel(const float* __restrict__ w1, const float* __restrict__ w2)
{
    int t = blockIdx.x * 256 + threadIdx.x;
    int ci   = t & 255;
    int co   = (t >> 8) & 255;
    int rest = t >> 16;                  // 0..17
    int tap  = rest % 9;
    int which = rest / 9;
    const float* w = which ? w2 : w1;
    g_wT[t] = __float2half_rn(w[(size_t)(co * 256 + ci) * 9 + tap]);
}

// ---------------------------------------------------------------------------
// Transpose: kin NCHW fp32 -> g_xT NHWC fp16 (padded frame rows zeroed)
// grid (67, 4, 16), 256 threads. Tile: 64 ch x 64 pixels.
// ---------------------------------------------------------------------------
__global__ void transpose_x_kernel(const float* __restrict__ kin)
{
    __shared__ float s[64][65];
    const int b = blockIdx.z, c0 = blockIdx.y * 64, n0 = blockIdx.x * 64;
    const int tid = threadIdx.x;

    if (n0 < 4096) {
#pragma unroll
        for (int i = 0; i < 16; ++i) {
            int idx = tid + i * 256, c = idx >> 6, p = idx & 63;
            s[c][p] = kin[((size_t)(b * C_ + c0 + c) << 12) + n0 + p];
        }
        __syncthreads();
#pragma unroll
        for (int i = 0; i < 8; ++i) {
            int idx = tid + i * 256, n = idx >> 5, cp = (idx & 31) * 2;
            __half2 v = __floats2half2_rn(s[cp][n], s[cp + 1][n]);
            *(__half2*)&g_xT[((size_t)b * FR_ + n0 + n) * C_ + c0 + cp] = v;
        }
    } else {
#pragma unroll
        for (int i = 0; i < 8; ++i) {
            int idx = tid + i * 256, n = idx >> 5, cp = (idx & 31) * 2;
            *(__half2*)&g_xT[((size_t)b * FR_ + n0 + n) * C_ + c0 + cp] =
                __floats2half2_rn(0.f, 0.f);
        }
    }
}

// ---------------------------------------------------------------------------
// Implicit-GEMM conv via mma.sync fp16 (m16n8k16) + 2-stage cp.async + ldmatrix.
// Block: 256 threads (8 warps, 2 M-warps x 4 N-warps), 3 CTAs/SM.
// CTA tile: M=128 pixels, N=128 couts. K-loop: 9 taps x 4 chunks of 64 cin.
// Warp tile: m64 x n32 = 4x4 mma x 4 k16-steps per chunk.
// Mainloop (one barrier/iter): wait(0) -> sync -> stage(it+1) -> compute(it).
// FIRST: epilogue lrelu+bias -> g_h1T.  !FIRST: lrelu+bias + masked pool sum.
// ---------------------------------------------------------------------------
template <bool FIRST>
__global__ __launch_bounds__(256, 3)
void conv_mma_kernel(const float* __restrict__ cbias)
{
    extern __shared__ __align__(16) char dsm[];
    __shared__ float sRed[2][128];

    const uint32_t sb = smem_u32(dsm);
    const int tid  = threadIdx.x;
    const int lane = tid & 31;
    const int wid  = tid >> 5;
    const int mwarp = wid >> 2;          // 0..1  (pixel 64-row half)
    const int nwarp = wid & 3;           // 0..3  (cout 32-col quarter)
    const int gid   = lane >> 2;         // 0..7
    const int tig   = lane & 3;          // 0..3

    const int ntile = blockIdx.x;
    const int b     = blockIdx.y;
    const int co0   = blockIdx.z * 128;
    const int n0    = ntile * 128;

    const __half* __restrict__ src  = FIRST ? g_xT : g_h1T;
    const __half* __restrict__ wsrc = g_wT + (FIRST ? 0 : (size_t)9 * 256 * 256);

    // staging: thread -> row rowS (0..127), 64B half (32 halves)
    const int rowS  = tid >> 1;
    const int halfS = (tid & 1) * 32;    // element offset within 64-half row
    const uint32_t stA = sb + (uint32_t)rowS * ROWB_ + (uint32_t)(tid & 1) * 64;
    const uint32_t stB = stA + TILEB_;

    // ldmatrix lane addresses (within tile) — validated b16 fragment layout
    const uint32_t aAddr = sb + (uint32_t)(mwarp * 64 + (lane & 15)) * ROWB_
                              + (uint32_t)(lane >> 4) * 16;
    const uint32_t bAddr = sb + TILEB_
                              + (uint32_t)(nwarp * 32 + ((lane >> 4) << 3) + (lane & 7)) * ROWB_
                              + (uint32_t)((lane >> 3) & 1) * 16;

    float acc[4][4][4];
#pragma unroll
    for (int mi = 0; mi < 4; ++mi)
#pragma unroll
        for (int ni = 0; ni < 4; ++ni)
#pragma unroll
            for (int j = 0; j < 4; ++j) acc[mi][ni][j] = 0.f;

    auto stage = [&](int it, int buf) {
        const int tap = it >> 2, ck = it & 3, cb = ck * 64;
        const int shift = (tap / 3) * 64 + (tap % 3);
        const uint32_t o = (uint32_t)buf * BUFB_;
        const __half* gA = src + ((size_t)(b * FR_ + n0 + shift + rowS)) * C_ + cb + halfS;
        const __half* gB = wsrc + ((size_t)(tap * 256 + co0 + rowS)) * C_ + cb + halfS;
#pragma unroll
        for (int j = 0; j < 4; ++j) cp16(stA + o + j * 16, gA + j * 8);
#pragma unroll
        for (int j = 0; j < 4; ++j) cp16(stB + o + j * 16, gB + j * 8);
    };

    // prologue: fill stage 0
    stage(0, 0); CP_COMMIT();

#pragma unroll 1
    for (int it = 0; it < 36; ++it) {
        CP_WAIT0();            // buf 'it' resident
        __syncthreads();       // + all warps done reading buf (it-1)&1

        if (it < 35) {
            stage(it + 1, (it + 1) & 1);   // overwrites buf read in it-1 (safe)
            CP_COMMIT();
        }

        const uint32_t Ab = aAddr + (uint32_t)(it & 1) * BUFB_;
        const uint32_t Bb = bAddr + (uint32_t)(it & 1) * BUFB_;

#pragma unroll
        for (int ks = 0; ks < 4; ++ks) {          // k16 steps: 4 x 32B columns
            uint32_t af[4][4];
#pragma unroll
            for (int mi = 0; mi < 4; ++mi)
                LDSM_X4(af[mi], Ab + (uint32_t)mi * (16 * ROWB_) + (uint32_t)ks * 32);
            uint32_t bf[4][2];
#pragma unroll
            for (int np = 0; np < 2; ++np) {
                uint32_t t4[4];
                LDSM_X4(t4, Bb + (uint32_t)np * (16 * ROWB_) + (uint32_t)ks * 32);
                bf[np * 2][0]     = t4[0]; bf[np * 2][1]     = t4[1];
                bf[np * 2 + 1][0] = t4[2]; bf[np * 2 + 1][1] = t4[3];
            }
#pragma unroll
            for (int mi = 0; mi < 4; ++mi)
#pragma unroll
                for (int ni = 0; ni < 4; ++ni)
                    MMA_F16(acc[mi][ni], af[mi], bf[ni]);
        }
    }

    // ---- epilogue ----
    const int prow = mwarp * 64 + gid;                 // pixel row within tile (+8 for c2/c3)
    const int ccol = co0 + nwarp * 32 + tig * 2;       // cout (pair)

    float bv0[4], bv1[4];
#pragma unroll
    for (int ni = 0; ni < 4; ++ni) { bv0[ni] = cbias[ccol + ni * 8]; bv1[ni] = cbias[ccol + ni * 8 + 1]; }

    if (FIRST) {
#pragma unroll
        for (int mi = 0; mi < 4; ++mi) {
            int na = n0 + prow + mi * 16;
            int nb = na + 8;
#pragma unroll
            for (int ni = 0; ni < 4; ++ni) {
                int cc = ccol + ni * 8;
                __half2 va = __floats2half2_rn(lrelu(acc[mi][ni][0] + bv0[ni]),
                                               lrelu(acc[mi][ni][1] + bv1[ni]));
                __half2 vb = __floats2half2_rn(lrelu(acc[mi][ni][2] + bv0[ni]),
                                               lrelu(acc[mi][ni][3] + bv1[ni]));
                *(__half2*)&g_h1T[((size_t)(b * FR_ + na)) * C_ + cc] = va;
                *(__half2*)&g_h1T[((size_t)(b * FR_ + nb)) * C_ + cc] = vb;
            }
        }
    } else {
        float s0[4], s1[4];
#pragma unroll
        for (int ni = 0; ni < 4; ++ni) { s0[ni] = 0.f; s1[ni] = 0.f; }
#pragma unroll
        for (int mi = 0; mi < 4; ++mi) {
            int na = n0 + prow + mi * 16;
            int nb = na + 8;
            bool va = (na & 63) < 60;
            bool vb = (nb & 63) < 60;
#pragma unroll
            for (int ni = 0; ni < 4; ++ni) {
                if (va) { s0[ni] += lrelu(acc[mi][ni][0] + bv0[ni]);
                          s1[ni] += lrelu(acc[mi][ni][1] + bv1[ni]); }
                if (vb) { s0[ni] += lrelu(acc[mi][ni][2] + bv0[ni]);
                          s1[ni] += lrelu(acc[mi][ni][3] + bv1[ni]); }
            }
        }
#pragma unroll
        for (int off = 4; off <= 16; off <<= 1)
#pragma unroll
            for (int ni = 0; ni < 4; ++ni) {
                s0[ni] += __shfl_xor_sync(0xFFFFFFFFu, s0[ni], off);
                s1[ni] += __shfl_xor_sync(0xFFFFFFFFu, s1[ni], off);
            }
        if (lane < 4) {
#pragma unroll
            for (int ni = 0; ni < 4; ++ni) {
                sRed[mwarp][nwarp * 32 + ni * 8 + lane * 2]     = s0[ni];
                sRed[mwarp][nwarp * 32 + ni * 8 + lane * 2 + 1] = s1[ni];
            }
        }
        __syncthreads();
        if (tid < 128)
            g_ppart[((size_t)ntile * B_ + b) * C_ + co0 + tid] = sRed[0][tid] + sRed[1][tid];
    }
}

// ---------------------------------------------------------------------------
// reduce 30 tile partials -> pooled p[b][c] (divide by 60*60)
// ---------------------------------------------------------------------------
__global__ void reduce_p_kernel()
{
    int i = blockIdx.x * 256 + threadIdx.x;
    float s = 0.f;
#pragma unroll
    for (int t = 0; t < NT2_; ++t) s += g_ppart[(size_t)t * (B_ * C_) + i];
    g_p[i] = s * (1.0f / 3600.0f);
}

// ---------------------------------------------------------------------------
// kern[b][o] = sum_c p[b][c] * w3[o][c] + b3[o]
// ---------------------------------------------------------------------------
__global__ void kern_gemm_kernel(const float* __restrict__ w3, const float* __restrict__ b3)
{
    __shared__ float sp[B_ * C_];
    const int tid = threadIdx.x, warp = tid >> 5, lane = tid & 31;
    for (int i = tid; i < B_ * C_; i += 256) sp[i] = g_p[i];
    __syncthreads();

    int o = blockIdx.x * 8 + warp;
    float wreg[8];
#pragma unroll
    for (int i = 0; i < 8; ++i) wreg[i] = w3[(size_t)o * C_ + lane + i * 32];
    float acc[B_];
#pragma unroll
    for (int b = 0; b < B_; ++b) acc[b] = 0.f;
#pragma unroll
    for (int i = 0; i < 8; ++i) {
        int c = lane + i * 32;
        float wv = wreg[i];
#pragma unroll
        for (int b = 0; b < B_; ++b) acc[b] = fmaf(wv, sp[b * C_ + c], acc[b]);
    }
#pragma unroll
    for (int off = 16; off > 0; off >>= 1)
#pragma unroll
        for (int b = 0; b < B_; ++b) acc[b] += __shfl_xor_sync(0xFFFFFFFFu, acc[b], off);
    if (lane == 0) {
        float bb = b3[o];
#pragma unroll
        for (int b = 0; b < B_; ++b) g_kern[b * (9 * C_) + o] = acc[b] + bb;
    }
}

// ---------------------------------------------------------------------------
// Depthwise 3x3 SAME conv, per-(b,c) kernel + bias. One block per (b,c).
// ---------------------------------------------------------------------------
__global__ __launch_bounds__(256)
void dwconv_kernel(const float* __restrict__ x, const float* __restrict__ bias,
                   float* __restrict__ out)
{
    __shared__ float sx[H_ * W_];
    __shared__ float sk[9];
    const int tid = threadIdx.x;
    const int bc = blockIdx.x, b = bc >> 8, c = bc & 255;

    const float* xin = x + (size_t)bc * (H_ * W_);
    for (int i = tid; i < (H_ * W_) / 4; i += 256)
        reinterpret_cast<float4*>(sx)[i] = reinterpret_cast<const float4*>(xin)[i];
    if (tid < 9) sk[tid] = g_kern[b * (9 * C_) + c * 9 + tid];
    __syncthreads();

    const float bv = bias[c];
    float k[9];
#pragma unroll
    for (int i = 0; i < 9; ++i) k[i] = sk[i];

    for (int p = tid; p < H_ * W_; p += 256) {
        int y = p >> 6, xx = p & 63;
        float s = bv;
#pragma unroll
        for (int ky = 0; ky < 3; ++ky) {
            int yy = y + ky - 1;
            if (yy < 0 || yy >= H_) continue;
#pragma unroll
            for (int kx = 0; kx < 3; ++kx) {
                int xc = xx + kx - 1;
                if (xc < 0 || xc >= W_) continue;
                s = fmaf(k[ky * 3 + kx], sx[yy * W_ + xc], s);
            }
        }
        out[(size_t)bc * (H_ * W_) + p] = s;
    }
}

// ---------------------------------------------------------------------------
// Launch. Inputs: x, kin, w1, b1, w2, b2, w3, b3, bias
// ---------------------------------------------------------------------------
extern "C" void kernel_launch(void* const* d_in, const int* in_sizes, int n_in,
                              void* d_out, int out_size)
{
    const float* x    = (const float*)d_in[0];
    const float* kin  = (const float*)d_in[1];
    const float* w1   = (const float*)d_in[2];
    const float* b1   = (const float*)d_in[3];
    const float* w2   = (const float*)d_in[4];
    const float* b2   = (const float*)d_in[5];
    const float* w3   = (const float*)d_in[6];
    const float* b3   = (const float*)d_in[7];
    const float* bias = (const float*)d_in[8];
    float* out = (float*)d_out;

    const int SMEM_CONV = NSTAGE_ * BUFB_;    // 73728 B dynamic
    cudaFuncSetAttribute(conv_mma_kernel<true>,  cudaFuncAttributeMaxDynamicSharedMemorySize, SMEM_CONV);
    cudaFuncSetAttribute(conv_mma_kernel<false>, cudaFuncAttributeMaxDynamicSharedMemorySize, SMEM_CONV);

    prep_w_kernel<<<2 * 9 * 256, 256>>>(w1, w2);
    transpose_x_kernel<<<dim3(67, 4, 16), 256>>>(kin);
    conv_mma_kernel<true ><<<dim3(NT1_, B_, 2), 256, SMEM_CONV>>>(b1);
    conv_mma_kernel<false><<<dim3(NT2_, B_, 2), 256, SMEM_CONV>>>(b2);
    reduce_p_kernel<<<B_ * C_ / 256, 256>>>();
    kern_gemm_kernel<<<(9 * C_) / 8, 256>>>(w3, b3);
    dwconv_kernel<<<B_ * C_, 256>>>(x, bias, out);
}

// round 16
// speedup vs baseline: 1.3756x; 1.3756x over previous
#include <cuda_runtime.h>
#include <cuda_fp16.h>
#include <cstdint>

// ---------------------------------------------------------------------------
// DynamicDWConv on GB300 (compute_103 PTX => mma.sync fp16 + cp.async + ldmatrix)
// conv3x3(VALID)+lrelu -> conv3x3(VALID)+lrelu -> global avg pool ->
// 1x1 kernel-gen -> depthwise 3x3 SAME + bias.   B=16, C=256, H=W=64.
//
// Convs as implicit GEMM: pixels=M, couts=N, K=cin, accumulated over 9 taps.
// NHWC pixel index n=y*64+x; tap (ky,kx) input = row slice at n+ky*64+kx.
// Round 15: R11 3-stage mainloop; warp tile widened to m64xn64 with 4 warps
// (128-thread CTA). LDSM smem-read amplification 2.7x -> 1.78x, 2x MMA ILP
// per warp, no register spills at 2 CTAs/SM.
// ---------------------------------------------------------------------------

#define B_   16
#define C_   256
#define H_   64
#define W_   64
#define FR_  4288            // 67*64 padded NHWC frame rows per batch
#define NT1_ 32              // conv1 pixel tiles (4096/128)
#define NT2_ 30              // conv2 pixel tiles (3840/128)

// smem tile geometry: 128 rows x 64 halves (128B), row stride 144B
#define ROWB_   144
#define TILEB_  18432        // 128*144 per A (or B) tile
#define BUFB_   36864        // A|B buffer
#define NSTAGE_ 3

// Scratch (__device__ globals; allocation-free). fp16 operands.
__device__ __half g_xT [(size_t)B_ * FR_ * C_];   // kin NHWC (~35MB)
__device__ __half g_h1T[(size_t)B_ * FR_ * C_];   // lrelu(conv1) NHWC
__device__ __half g_wT [2 * 9 * 256 * 256];       // [which][tap][cout][cin]
__device__ float g_ppart[NT2_ * B_ * C_];
__device__ float g_p[B_ * C_];
__device__ float g_kern[B_ * 9 * C_];

__device__ __forceinline__ float lrelu(float v) { return v > 0.f ? v : 0.1f * v; }
__device__ __forceinline__ uint32_t smem_u32(const void* p) {
    uint32_t a;
    asm("{ .reg .u64 t; cvta.to.shared.u64 t, %1; cvt.u32.u64 %0, t; }" : "=r"(a) : "l"(p));
    return a;
}
__device__ __forceinline__ void cp16(uint32_t s, const void* g) {
    asm volatile("cp.async.cg.shared.global [%0], [%1], 16;" :: "r"(s), "l"(g) : "memory");
}
#define CP_COMMIT() asm volatile("cp.async.commit_group;" ::: "memory")
#define CP_WAIT1()  asm volatile("cp.async.wait_group 1;" ::: "memory")
#define CP_WAIT0()  asm volatile("cp.async.wait_group 0;" ::: "memory")

#define LDSM_X4(r, addr) \
    asm volatile("ldmatrix.sync.aligned.m8n8.x4.shared.b16 {%0,%1,%2,%3}, [%4];" \
        : "=r"((r)[0]), "=r"((r)[1]), "=r"((r)[2]), "=r"((r)[3]) : "r"(addr))

#define MMA_F16(d, a, bq) \
    asm volatile("mma.sync.aligned.m16n8k16.row.col.f32.f16.f16.f32 " \
        "{%0,%1,%2,%3}, {%4,%5,%6,%7}, {%8,%9}, {%0,%1,%2,%3};" \
        : "+f"((d)[0]), "+f"((d)[1]), "+f"((d)[2]), "+f"((d)[3]) \
        : "r"((a)[0]), "r"((a)[1]), "r"((a)[2]), "r"((a)[3]), \
          "r"((bq)[0]), "r"((bq)[1]))

// ---------------------------------------------------------------------------
// Prep: w [cout][cin][3][3] fp32 -> g_wT[which][tap][cout][cin] fp16
// ---------------------------------------------------------------------------
__global__ void prep_w_kernel(const float* __restrict__ w1, const float* __restrict__ w2)
{
    int t = blockIdx.x * 256 + threadIdx.x;
    int ci   = t & 255;
    int co   = (t >> 8) & 255;
    int rest = t >> 16;                  // 0..17
    int tap  = rest % 9;
    int which = rest / 9;
    const float* w = which ? w2 : w1;
    g_wT[t] = __float2half_rn(w[(size_t)(co * 256 + ci) * 9 + tap]);
}

// ---------------------------------------------------------------------------
// Transpose: kin NCHW fp32 -> g_xT NHWC fp16 (padded frame rows zeroed)
// grid (67, 4, 16), 256 threads. Tile: 64 ch x 64 pixels.
// ---------------------------------------------------------------------------
__global__ void transpose_x_kernel(const float* __restrict__ kin)
{
    __shared__ float s[64][65];
    const int b = blockIdx.z, c0 = blockIdx.y * 64, n0 = blockIdx.x * 64;
    const int tid = threadIdx.x;

    if (n0 < 4096) {
#pragma unroll
        for (int i = 0; i < 16; ++i) {
            int idx = tid + i * 256, c = idx >> 6, p = idx & 63;
            s[c][p] = kin[((size_t)(b * C_ + c0 + c) << 12) + n0 + p];
        }
        __syncthreads();
#pragma unroll
        for (int i = 0; i < 8; ++i) {
            int idx = tid + i * 256, n = idx >> 5, cp = (idx & 31) * 2;
            __half2 v = __floats2half2_rn(s[cp][n], s[cp + 1][n]);
            *(__half2*)&g_xT[((size_t)b * FR_ + n0 + n) * C_ + c0 + cp] = v;
        }
    } else {
#pragma unroll
        for (int i = 0; i < 8; ++i) {
            int idx = tid + i * 256, n = idx >> 5, cp = (idx & 31) * 2;
            *(__half2*)&g_xT[((size_t)b * FR_ + n0 + n) * C_ + c0 + cp] =
                __floats2half2_rn(0.f, 0.f);
        }
    }
}

// ---------------------------------------------------------------------------
// Implicit-GEMM conv via mma.sync fp16 (m16n8k16) + 3-stage cp.async + ldmatrix.
// Block: 128 threads (4 warps, 2 M-warps x 2 N-warps). Warp tile m64 x n64.
// CTA tile: M=128 pixels, N=128 couts. K-loop: 9 taps x 4 chunks of 64 cin.
// Dynamic smem: 3 buffers of (A tile | B tile), 128 rows x 144B each.
// Mainloop (one barrier/iter): wait(1) -> sync -> stage(it+2) -> compute(it).
// FIRST: epilogue lrelu+bias -> g_h1T.  !FIRST: lrelu+bias + masked pool sum.
// ---------------------------------------------------------------------------
template <bool FIRST>
__global__ __launch_bounds__(128)
void conv_mma_kernel(const float* __restrict__ cbias)
{
    extern __shared__ __align__(16) char dsm[];
    __shared__ float sRed[2][128];

    const uint32_t sb = smem_u32(dsm);
    const int tid  = threadIdx.x;
    const int lane = tid & 31;
    const int wid  = tid >> 5;
    const int mwarp = wid >> 1;          // 0..1  (pixel 64-row half)
    const int nwarp = wid & 1;           // 0..1  (cout 64-col half)
    const int gid   = lane >> 2;         // 0..7
    const int tig   = lane & 3;          // 0..3

    const int ntile = blockIdx.x;
    const int b     = blockIdx.y;
    const int co0   = blockIdx.z * 128;
    const int n0    = ntile * 128;

    const __half* __restrict__ src  = FIRST ? g_xT : g_h1T;
    const __half* __restrict__ wsrc = g_wT + (FIRST ? 0 : (size_t)9 * 256 * 256);

    // staging: thread -> one full 128B row of A and of B
    const int rowS = tid;                // 0..127
    const uint32_t stA = sb + (uint32_t)rowS * ROWB_;
    const uint32_t stB = stA + TILEB_;

    // ldmatrix lane addresses (within tile) — validated b16 fragment layout
    const uint32_t aAddr = sb + (uint32_t)(mwarp * 64 + (lane & 15)) * ROWB_
                              + (uint32_t)(lane >> 4) * 16;
    const uint32_t bAddr = sb + TILEB_
                              + (uint32_t)(nwarp * 64 + ((lane >> 4) << 3) + (lane & 7)) * ROWB_
                              + (uint32_t)((lane >> 3) & 1) * 16;

    float acc[4][8][4];
#pragma unroll
    for (int mi = 0; mi < 4; ++mi)
#pragma unroll
        for (int ni = 0; ni < 8; ++ni)
#pragma unroll
            for (int j = 0; j < 4; ++j) acc[mi][ni][j] = 0.f;

    auto stage = [&](int it, int buf) {
        const int tap = it >> 2, ck = it & 3, cb = ck * 64;
        const int shift = (tap / 3) * 64 + (tap % 3);
        const uint32_t o = (uint32_t)buf * BUFB_;
        const __half* gA = src + ((size_t)(b * FR_ + n0 + shift + rowS)) * C_ + cb;
        const __half* gB = wsrc + ((size_t)(tap * 256 + co0 + rowS)) * C_ + cb;
#pragma unroll
        for (int j = 0; j < 8; ++j) cp16(stA + o + j * 16, gA + j * 8);
#pragma unroll
        for (int j = 0; j < 8; ++j) cp16(stB + o + j * 16, gB + j * 8);
    };

    // prologue: fill stages 0 and 1
    stage(0, 0); CP_COMMIT();
    stage(1, 1); CP_COMMIT();

    int buf = 0;
#pragma unroll 1
    for (int it = 0; it < 36; ++it) {
        CP_WAIT1();            // group for buf 'it' complete
        __syncthreads();       // visibility + all warps done reading buf (it-1)%3

        if (it < 34) {
            int nb = buf + 2; if (nb >= NSTAGE_) nb -= NSTAGE_;
            stage(it + 2, nb);
        }
        CP_COMMIT();

        const uint32_t Ab = aAddr + (uint32_t)buf * BUFB_;
        const uint32_t Bb = bAddr + (uint32_t)buf * BUFB_;

#pragma unroll
        for (int ks = 0; ks < 4; ++ks) {          // k16 steps: 4 x 32B columns
            uint32_t af[4][4];
#pragma unroll
            for (int mi = 0; mi < 4; ++mi)
                LDSM_X4(af[mi], Ab + (uint32_t)mi * (16 * ROWB_) + (uint32_t)ks * 32);
            uint32_t bf[8][2];
#pragma unroll
            for (int np = 0; np < 4; ++np) {
                uint32_t t4[4];
                LDSM_X4(t4, Bb + (uint32_t)np * (16 * ROWB_) + (uint32_t)ks * 32);
                bf[np * 2][0]     = t4[0]; bf[np * 2][1]     = t4[1];
                bf[np * 2 + 1][0] = t4[2]; bf[np * 2 + 1][1] = t4[3];
            }
#pragma unroll
            for (int mi = 0; mi < 4; ++mi)
#pragma unroll
                for (int ni = 0; ni < 8; ++ni)
                    MMA_F16(acc[mi][ni], af[mi], bf[ni]);
        }

        if (++buf >= NSTAGE_) buf = 0;
    }

    // ---- epilogue ----
    const int prow = mwarp * 64 + gid;                 // pixel row within tile (+8 for c2/c3)
    const int ccol = co0 + nwarp * 64 + tig * 2;       // cout (pair)

    float bv0[8], bv1[8];
#pragma unroll
    for (int ni = 0; ni < 8; ++ni) { bv0[ni] = cbias[ccol + ni * 8]; bv1[ni] = cbias[ccol + ni * 8 + 1]; }

    if (FIRST) {
#pragma unroll
        for (int mi = 0; mi < 4; ++mi) {
            int na = n0 + prow + mi * 16;
            int nb = na + 8;
#pragma unroll
            for (int ni = 0; ni < 8; ++ni) {
                int cc = ccol + ni * 8;
                __half2 va = __floats2half2_rn(lrelu(acc[mi][ni][0] + bv0[ni]),
                                               lrelu(acc[mi][ni][1] + bv1[ni]));
                __half2 vb = __floats2half2_rn(lrelu(acc[mi][ni][2] + bv0[ni]),
                                               lrelu(acc[mi][ni][3] + bv1[ni]));
                *(__half2*)&g_h1T[((size_t)(b * FR_ + na)) * C_ + cc] = va;
                *(__half2*)&g_h1T[((size_t)(b * FR_ + nb)) * C_ + cc] = vb;
            }
        }
    } else {
        float s0[8], s1[8];
#pragma unroll
        for (int ni = 0; ni < 8; ++ni) { s0[ni] = 0.f; s1[ni] = 0.f; }
#pragma unroll
        for (int mi = 0; mi < 4; ++mi) {
            int na = n0 + prow + mi * 16;
            int nb = na + 8;
            bool va = (na & 63) < 60;
            bool vb = (nb & 63) < 60;
#pragma unroll
            for (int ni = 0; ni < 8; ++ni) {
                if (va) { s0[ni] += lrelu(acc[mi][ni][0] + bv0[ni]);
                          s1[ni] += lrelu(acc[mi][ni][1] + bv1[ni]); }
                if (vb) { s0[ni] += lrelu(acc[mi][ni][2] + bv0[ni]);
                          s1[ni] += lrelu(acc[mi][ni][3] + bv1[ni]); }
            }
        }
#pragma unroll
        for (int off = 4; off <= 16; off <<= 1)
#pragma unroll
            for (int ni = 0; ni < 8; ++ni) {
                s0[ni] += __shfl_xor_sync(0xFFFFFFFFu, s0[ni], off);
                s1[ni] += __shfl_xor_sync(0xFFFFFFFFu, s1[ni], off);
            }
        if (lane < 4) {
#pragma unroll
            for (int ni = 0; ni < 8; ++ni) {
                sRed[mwarp][nwarp * 64 + ni * 8 + lane * 2]     = s0[ni];
                sRed[mwarp][nwarp * 64 + ni * 8 + lane * 2 + 1] = s1[ni];
            }
        }
        __syncthreads();
        if (tid < 128)
            g_ppart[((size_t)ntile * B_ + b) * C_ + co0 + tid] = sRed[0][tid] + sRed[1][tid];
    }
}

// ---------------------------------------------------------------------------
// reduce 30 tile partials -> pooled p[b][c] (divide by 60*60)
// ---------------------------------------------------------------------------
__global__ void reduce_p_kernel()
{
    int i = blockIdx.x * 256 + threadIdx.x;
    float s = 0.f;
#pragma unroll
    for (int t = 0; t < NT2_; ++t) s += g_ppart[(size_t)t * (B_ * C_) + i];
    g_p[i] = s * (1.0f / 3600.0f);
}

// ---------------------------------------------------------------------------
// kern[b][o] = sum_c p[b][c] * w3[o][c] + b3[o]
// ---------------------------------------------------------------------------
__global__ void kern_gemm_kernel(const float* __restrict__ w3, const float* __restrict__ b3)
{
    __shared__ float sp[B_ * C_];
    const int tid = threadIdx.x, warp = tid >> 5, lane = tid & 31;
    for (int i = tid; i < B_ * C_; i += 256) sp[i] = g_p[i];
    __syncthreads();

    int o = blockIdx.x * 8 + warp;
    float wreg[8];
#pragma unroll
    for (int i = 0; i < 8; ++i) wreg[i] = w3[(size_t)o * C_ + lane + i * 32];
    float acc[B_];
#pragma unroll
    for (int b = 0; b < B_; ++b) acc[b] = 0.f;
#pragma unroll
    for (int i = 0; i < 8; ++i) {
        int c = lane + i * 32;
        float wv = wreg[i];
#pragma unroll
        for (int b = 0; b < B_; ++b) acc[b] = fmaf(wv, sp[b * C_ + c], acc[b]);
    }
#pragma unroll
    for (int off = 16; off > 0; off >>= 1)
#pragma unroll
        for (int b = 0; b < B_; ++b) acc[b] += __shfl_xor_sync(0xFFFFFFFFu, acc[b], off);
    if (lane == 0) {
        float bb = b3[o];
#pragma unroll
        for (int b = 0; b < B_; ++b) g_kern[b * (9 * C_) + o] = acc[b] + bb;
    }
}

// ---------------------------------------------------------------------------
// Depthwise 3x3 SAME conv, per-(b,c) kernel + bias. One block per (b,c).
// ---------------------------------------------------------------------------
__global__ __launch_bounds__(256)
void dwconv_kernel(const float* __restrict__ x, const float* __restrict__ bias,
                   float* __restrict__ out)
{
    __shared__ float sx[H_ * W_];
    __shared__ float sk[9];
    const int tid = threadIdx.x;
    const int bc = blockIdx.x, b = bc >> 8, c = bc & 255;

    const float* xin = x + (size_t)bc * (H_ * W_);
    for (int i = tid; i < (H_ * W_) / 4; i += 256)
        reinterpret_cast<float4*>(sx)[i] = reinterpret_cast<const float4*>(xin)[i];
    if (tid < 9) sk[tid] = g_kern[b * (9 * C_) + c * 9 + tid];
    __syncthreads();

    const float bv = bias[c];
    float k[9];
#pragma unroll
    for (int i = 0; i < 9; ++i) k[i] = sk[i];

    for (int p = tid; p < H_ * W_; p += 256) {
        int y = p >> 6, xx = p & 63;
        float s = bv;
#pragma unroll
        for (int ky = 0; ky < 3; ++ky) {
            int yy = y + ky - 1;
            if (yy < 0 || yy >= H_) continue;
#pragma unroll
            for (int kx = 0; kx < 3; ++kx) {
                int xc = xx + kx - 1;
                if (xc < 0 || xc >= W_) continue;
                s = fmaf(k[ky * 3 + kx], sx[yy * W_ + xc], s);
            }
        }
        out[(size_t)bc * (H_ * W_) + p] = s;
    }
}

// ---------------------------------------------------------------------------
// Launch. Inputs: x, kin, w1, b1, w2, b2, w3, b3, bias
// ---------------------------------------------------------------------------
extern "C" void kernel_launch(void* const* d_in, const int* in_sizes, int n_in,
                              void* d_out, int out_size)
{
    const float* x    = (const float*)d_in[0];
    const float* kin  = (const float*)d_in[1];
    const float* w1   = (const float*)d_in[2];
    const float* b1   = (const float*)d_in[3];
    const float* w2   = (const float*)d_in[4];
    const float* b2   = (const float*)d_in[5];
    const float* w3   = (const float*)d_in[6];
    const float* b3   = (const float*)d_in[7];
    const float* bias = (const float*)d_in[8];
    float* out = (float*)d_out;

    const int SMEM_CONV = NSTAGE_ * BUFB_;    // 110592 B dynamic
    cudaFuncSetAttribute(conv_mma_kernel<true>,  cudaFuncAttributeMaxDynamicSharedMemorySize, SMEM_CONV);
    cudaFuncSetAttribute(conv_mma_kernel<false>, cudaFuncAttributeMaxDynamicSharedMemorySize, SMEM_CONV);

    prep_w_kernel<<<2 * 9 * 256, 256>>>(w1, w2);
    transpose_x_kernel<<<dim3(67, 4, 16), 256>>>(kin);
    conv_mma_kernel<true ><<<dim3(NT1_, B_, 2), 128, SMEM_CONV>>>(b1);
    conv_mma_kernel<false><<<dim3(NT2_, B_, 2), 128, SMEM_CONV>>>(b2);
    reduce_p_kernel<<<B_ * C_ / 256, 256>>>();
    kern_gemm_kernel<<<(9 * C_) / 8, 256>>>(w3, b3);
    dwconv_kernel<<<B_ * C_, 256>>>(x, bias, out);
}